// round 3
// baseline (speedup 1.0000x reference)
#include <cuda_runtime.h>
#include <cuda_bf16.h>
#include <cstdint>
#include <cstddef>

// Problem dims (fixed for this problem instance)
#define NROWS 8192   // B*S tokens
#define DIN   4096   // in features (K)
#define NOUT  4096   // out features (N)

// ---------------- scratch (device globals; no allocs allowed) ----------------
static __device__ signed char g_xq[(size_t)NROWS * DIN];   // int8 quantized activations
static __device__ signed char g_wq[(size_t)NOUT * DIN];    // int8 ternary weights
static __device__ float g_xscale[NROWS];
static __device__ float g_partials[1024];
static __device__ float g_wscale;

// ---------------- PTX helpers ----------------
__device__ __forceinline__ uint32_t smem_u32(const void* p) {
    uint32_t a;
    asm("{ .reg .u64 t; cvta.to.shared.u64 t, %1; cvt.u32.u64 %0, t; }" : "=r"(a) : "l"(p));
    return a;
}
__device__ __forceinline__ void cp_async16(uint32_t dst, const void* src) {
    size_t gsrc = __cvta_generic_to_global(src);
    asm volatile("cp.async.cg.shared.global [%0], [%1], 16;" :: "r"(dst), "l"(gsrc) : "memory");
}
#define CP_COMMIT() asm volatile("cp.async.commit_group;" ::: "memory")
#define CP_WAIT(n)  asm volatile("cp.async.wait_group %0;" :: "n"(n) : "memory")

__device__ __forceinline__ void ldsm_x4(uint32_t& r0, uint32_t& r1, uint32_t& r2, uint32_t& r3,
                                        uint32_t addr) {
    asm volatile("ldmatrix.sync.aligned.m8n8.x4.shared.b16 {%0,%1,%2,%3}, [%4];"
                 : "=r"(r0), "=r"(r1), "=r"(r2), "=r"(r3) : "r"(addr));
}
__device__ __forceinline__ void mma_s8(int* c, const uint32_t* a, const uint32_t* b) {
    asm volatile(
        "mma.sync.aligned.m16n8k32.row.col.s32.s8.s8.s32 "
        "{%0,%1,%2,%3}, {%4,%5,%6,%7}, {%8,%9}, {%0,%1,%2,%3};"
        : "+r"(c[0]), "+r"(c[1]), "+r"(c[2]), "+r"(c[3])
        : "r"(a[0]), "r"(a[1]), "r"(a[2]), "r"(a[3]), "r"(b[0]), "r"(b[1]));
}

// ---------------- block sum (256 threads) ----------------
__device__ __forceinline__ float block_sum_256(float v, float* sh) {
    #pragma unroll
    for (int o = 16; o; o >>= 1) v += __shfl_xor_sync(0xFFFFFFFFu, v, o);
    int tid = threadIdx.x;
    if ((tid & 31) == 0) sh[tid >> 5] = v;
    __syncthreads();
    if (tid < 8) {
        float t = sh[tid];
        #pragma unroll
        for (int o = 4; o; o >>= 1) t += __shfl_xor_sync(0x000000FFu, t, o);
        if (tid == 0) sh[8] = t;
    }
    __syncthreads();
    float r = sh[8];
    __syncthreads();
    return r;
}

// ---------------- weight scale: two-pass deterministic abs-mean ----------------
__global__ void __launch_bounds__(256) wabs_partial_kernel(const float* __restrict__ w) {
    __shared__ float sh[9];
    const float4* wf = (const float4*)w;
    float s = 0.0f;
    for (int i = blockIdx.x * 256 + threadIdx.x; i < (DIN / 4) * NOUT; i += 1024 * 256) {
        float4 t = wf[i];
        s += fabsf(t.x) + fabsf(t.y) + fabsf(t.z) + fabsf(t.w);
    }
    s = block_sum_256(s, sh);
    if (threadIdx.x == 0) g_partials[blockIdx.x] = s;
}
__global__ void __launch_bounds__(256) wabs_final_kernel() {
    __shared__ float sh[9];
    float s = 0.0f;
    for (int i = threadIdx.x; i < 1024; i += 256) s += g_partials[i];
    s = block_sum_256(s, sh);
    if (threadIdx.x == 0) {
        float mean = s * (1.0f / ((float)NOUT * (float)DIN));
        g_wscale = fmaxf(mean, 1e-5f);
    }
}

// ---------------- weight ternary quant -> int8 ----------------
__global__ void __launch_bounds__(256) wquant_kernel(const float* __restrict__ w) {
    float rws = 1.0f / g_wscale;
    const float4* wf = (const float4*)w;
    uint32_t* wq = (uint32_t*)g_wq;
    for (int i = blockIdx.x * 256 + threadIdx.x; i < (DIN / 4) * NOUT; i += 4096 * 256) {
        float4 t = wf[i];
        int q0 = (int)fminf(fmaxf(rintf(t.x * rws), -1.0f), 1.0f);
        int q1 = (int)fminf(fmaxf(rintf(t.y * rws), -1.0f), 1.0f);
        int q2 = (int)fminf(fmaxf(rintf(t.z * rws), -1.0f), 1.0f);
        int q3 = (int)fminf(fmaxf(rintf(t.w * rws), -1.0f), 1.0f);
        wq[i] = (q0 & 0xFF) | ((q1 & 0xFF) << 8) | ((q2 & 0xFF) << 16) | ((q3 & 0xFF) << 24);
    }
}

// ---------------- LayerNorm + per-token absmax int8 quant (single-pass stats) ----------------
__global__ void __launch_bounds__(256) ln_quant_kernel(const float* __restrict__ x) {
    __shared__ float sh_s[8], sh_s2[8], sh_mx[8], sh_mn[8];
    __shared__ float shb[4];  // mu, inv, rscale, (unused)
    int row = blockIdx.x;
    int tid = threadIdx.x;
    const float4* xr = (const float4*)(x + (size_t)row * DIN);
    float4 v[4];
    #pragma unroll
    for (int c = 0; c < 4; c++) v[c] = xr[tid + c * 256];

    float s = 0.0f, s2 = 0.0f, mx = -1e30f, mn = 1e30f;
    #pragma unroll
    for (int c = 0; c < 4; c++) {
        s += v[c].x + v[c].y + v[c].z + v[c].w;
        s2 += v[c].x * v[c].x + v[c].y * v[c].y + v[c].z * v[c].z + v[c].w * v[c].w;
        mx = fmaxf(mx, fmaxf(fmaxf(v[c].x, v[c].y), fmaxf(v[c].z, v[c].w)));
        mn = fminf(mn, fminf(fminf(v[c].x, v[c].y), fminf(v[c].z, v[c].w)));
    }
    #pragma unroll
    for (int o = 16; o; o >>= 1) {
        s  += __shfl_xor_sync(0xFFFFFFFFu, s, o);
        s2 += __shfl_xor_sync(0xFFFFFFFFu, s2, o);
        mx = fmaxf(mx, __shfl_xor_sync(0xFFFFFFFFu, mx, o));
        mn = fminf(mn, __shfl_xor_sync(0xFFFFFFFFu, mn, o));
    }
    if ((tid & 31) == 0) {
        int w = tid >> 5;
        sh_s[w] = s; sh_s2[w] = s2; sh_mx[w] = mx; sh_mn[w] = mn;
    }
    __syncthreads();
    if (tid < 8) {
        float ts = sh_s[tid], ts2 = sh_s2[tid], tmx = sh_mx[tid], tmn = sh_mn[tid];
        #pragma unroll
        for (int o = 4; o; o >>= 1) {
            ts  += __shfl_xor_sync(0x000000FFu, ts, o);
            ts2 += __shfl_xor_sync(0x000000FFu, ts2, o);
            tmx = fmaxf(tmx, __shfl_xor_sync(0x000000FFu, tmx, o));
            tmn = fminf(tmn, __shfl_xor_sync(0x000000FFu, tmn, o));
        }
        if (tid == 0) {
            float mu = ts * (1.0f / DIN);
            float var = ts2 * (1.0f / DIN) - mu * mu + 1e-5f;
            float inv = rsqrtf(var);
            inv = inv * (1.5f - 0.5f * var * inv * inv);  // Newton refine
            float amax = fmaxf(tmx - mu, mu - tmn) * inv;
            float scale = fmaxf(amax, 1e-5f) * (1.0f / 127.0f);
            shb[0] = mu; shb[1] = inv; shb[2] = 1.0f / scale;
            g_xscale[row] = scale;
        }
    }
    __syncthreads();
    float mu = shb[0], inv = shb[1], rs = shb[2];
    float k = inv * rs;

    uint32_t* qrow = (uint32_t*)(g_xq + (size_t)row * DIN);
    #pragma unroll
    for (int c = 0; c < 4; c++) {
        int q0 = (int)fminf(fmaxf(rintf((v[c].x - mu) * k), -128.0f), 127.0f);
        int q1 = (int)fminf(fmaxf(rintf((v[c].y - mu) * k), -128.0f), 127.0f);
        int q2 = (int)fminf(fmaxf(rintf((v[c].z - mu) * k), -128.0f), 127.0f);
        int q3 = (int)fminf(fmaxf(rintf((v[c].w - mu) * k), -128.0f), 127.0f);
        qrow[tid + c * 256] = (q0 & 0xFF) | ((q1 & 0xFF) << 8) | ((q2 & 0xFF) << 16) |
                              ((q3 & 0xFF) << 24);
    }
}

// ---------------- int8 mma.sync GEMM: [8192,4096] x [4096,4096]^T ----------------
// CTA tile 128x256, warp tile 64x64 (8 warps, 2x4), K chunk 64B, 4-stage cp.async.
// SMEM rows padded to 80B -> ldmatrix phases conflict-free.
static constexpr int BM = 128, BN = 256, BK = 64, STAGES = 4;
static constexpr int NK = DIN / BK;          // 64
static constexpr int PITCH = 80;             // bytes per smem row
static constexpr int ASTG = BM * PITCH;      // 10240
static constexpr int BSTG = BN * PITCH;      // 20480
static constexpr int STG = ASTG + BSTG;      // 30720
static constexpr int GEMM_SMEM = STAGES * STG;  // 122880

__device__ __forceinline__ void copy_stage(uint32_t sb, int s, int kc,
                                           const signed char* Ab,
                                           const signed char* Bb, int tid) {
    uint32_t stA = sb + s * STG;
    uint32_t stB = stA + ASTG;
    #pragma unroll
    for (int p = 0; p < 2; ++p) {  // A: 128 rows x 4 granules = 512
        int g = tid + p * 256;
        int r = g >> 2, c = g & 3;
        cp_async16(stA + r * PITCH + c * 16, Ab + (size_t)r * DIN + kc * BK + c * 16);
    }
    #pragma unroll
    for (int p = 0; p < 4; ++p) {  // B: 256 rows x 4 granules = 1024
        int g = tid + p * 256;
        int r = g >> 2, c = g & 3;
        cp_async16(stB + r * PITCH + c * 16, Bb + (size_t)r * DIN + kc * BK + c * 16);
    }
}

__global__ void __launch_bounds__(256, 1) gemm_kernel(float* __restrict__ out) {
    extern __shared__ __align__(128) char smem[];
    uint32_t sb = smem_u32(smem);
    int tid = threadIdx.x, wid = tid >> 5, lane = tid & 31;
    int nt = blockIdx.x, mt = blockIdx.y;
    int warp_m = wid & 1;    // 0..1 -> 64-row slab
    int warp_n = wid >> 1;   // 0..3 -> 64-col slab

    const signed char* Ab = g_xq + (size_t)mt * BM * DIN;
    const signed char* Bb = g_wq + (size_t)nt * BN * DIN;

    // ldmatrix lane-address offsets (within a stage)
    uint32_t aoff = (uint32_t)(warp_m * 64 + (lane & 15)) * PITCH + (uint32_t)(lane >> 4) * 16;
    uint32_t boff = (uint32_t)(warp_n * 64 + ((lane >> 4) & 1) * 8 + (lane & 7)) * PITCH +
                    (uint32_t)((lane >> 3) & 1) * 16;

    int acc[4][8][4];
    #pragma unroll
    for (int i = 0; i < 4; i++)
        #pragma unroll
        for (int j = 0; j < 8; j++)
            #pragma unroll
            for (int k = 0; k < 4; k++) acc[i][j][k] = 0;

    // prologue: stages 0..2
    #pragma unroll
    for (int s = 0; s < STAGES - 1; ++s) {
        copy_stage(sb, s, s, Ab, Bb, tid);
        CP_COMMIT();
    }

    for (int i = 0; i < NK; ++i) {
        CP_WAIT(STAGES - 2);
        __syncthreads();

        int j = i + (STAGES - 1);
        if (j < NK) copy_stage(sb, j % STAGES, j, Ab, Bb, tid);
        CP_COMMIT();  // commit every iter (possibly empty) to keep group count invariant

        int s = i % STAGES;
        uint32_t stA = sb + s * STG;
        uint32_t stB = stA + ASTG;
        #pragma unroll
        for (int ks = 0; ks < 2; ++ks) {  // two k32 substeps per 64B chunk
            uint32_t a[4][4];
            uint32_t b[8][2];
            #pragma unroll
            for (int im = 0; im < 4; ++im)
                ldsm_x4(a[im][0], a[im][1], a[im][2], a[im][3],
                        stA + aoff + im * 16 * PITCH + ks * 32);
            #pragma unroll
            for (int t = 0; t < 4; ++t)
                ldsm_x4(b[2 * t][0], b[2 * t][1], b[2 * t + 1][0], b[2 * t + 1][1],
                        stB + boff + t * 16 * PITCH + ks * 32);
            #pragma unroll
            for (int im = 0; im < 4; ++im)
                #pragma unroll
                for (int in = 0; in < 8; ++in)
                    mma_s8(acc[im][in], a[im], b[in]);
        }
    }

    // epilogue: s32 -> f32 with w_scale * x_scale[m]
    float ws = g_wscale;
    int m0 = mt * BM + warp_m * 64 + (lane >> 2);
    int n0 = nt * BN + warp_n * 64 + (lane & 3) * 2;
    #pragma unroll
    for (int im = 0; im < 4; ++im) {
        int r0 = m0 + im * 16;
        int r1 = r0 + 8;
        float f0 = ws * g_xscale[r0];
        float f1 = ws * g_xscale[r1];
        float* o0 = out + (size_t)r0 * NOUT + n0;
        float* o1 = out + (size_t)r1 * NOUT + n0;
        #pragma unroll
        for (int in = 0; in < 8; ++in) {
            float2 v0, v1;
            v0.x = (float)acc[im][in][0] * f0;
            v0.y = (float)acc[im][in][1] * f0;
            v1.x = (float)acc[im][in][2] * f1;
            v1.y = (float)acc[im][in][3] * f1;
            *(float2*)(o0 + in * 8) = v0;
            *(float2*)(o1 + in * 8) = v1;
        }
    }
}

// ---------------- launch ----------------
extern "C" void kernel_launch(void* const* d_in, const int* in_sizes, int n_in,
                              void* d_out, int out_size) {
    const float* x = (const float*)d_in[0];
    const float* w = (const float*)d_in[1];
    float* out = (float*)d_out;

    cudaFuncSetAttribute(gemm_kernel, cudaFuncAttributeMaxDynamicSharedMemorySize, GEMM_SMEM);

    wabs_partial_kernel<<<1024, 256>>>(w);
    wabs_final_kernel<<<1, 256>>>();
    wquant_kernel<<<4096, 256>>>(w);
    ln_quant_kernel<<<NROWS, 256>>>(x);
    gemm_kernel<<<dim3(NOUT / BN, NROWS / BM), 256, GEMM_SMEM>>>(out);
}

// round 4
// speedup vs baseline: 1.1003x; 1.1003x over previous
#include <cuda_runtime.h>
#include <cuda_bf16.h>
#include <cstdint>
#include <cstddef>

// Problem dims (fixed for this problem instance)
#define NROWS 8192   // B*S tokens
#define DIN   4096   // in features (K)
#define NOUT  4096   // out features (N)

// ---------------- scratch (device globals; no allocs allowed) ----------------
static __device__ signed char g_xq[(size_t)NROWS * DIN];   // int8 quantized activations
static __device__ signed char g_wq[(size_t)NOUT * DIN];    // int8 ternary weights
static __device__ float g_xscale[NROWS];
static __device__ float g_partials[1024];
static __device__ float g_wscale;

// ---------------- PTX helpers ----------------
__device__ __forceinline__ uint32_t smem_u32(const void* p) {
    uint32_t a;
    asm("{ .reg .u64 t; cvta.to.shared.u64 t, %1; cvt.u32.u64 %0, t; }" : "=r"(a) : "l"(p));
    return a;
}
__device__ __forceinline__ void cp_async16(uint32_t dst, const void* src) {
    size_t gsrc = __cvta_generic_to_global(src);
    asm volatile("cp.async.cg.shared.global [%0], [%1], 16;" :: "r"(dst), "l"(gsrc) : "memory");
}
#define CP_COMMIT() asm volatile("cp.async.commit_group;" ::: "memory")
#define CP_WAIT(n)  asm volatile("cp.async.wait_group %0;" :: "n"(n) : "memory")

__device__ __forceinline__ void ldsm_x4(uint32_t& r0, uint32_t& r1, uint32_t& r2, uint32_t& r3,
                                        uint32_t addr) {
    asm volatile("ldmatrix.sync.aligned.m8n8.x4.shared.b16 {%0,%1,%2,%3}, [%4];"
                 : "=r"(r0), "=r"(r1), "=r"(r2), "=r"(r3) : "r"(addr));
}
__device__ __forceinline__ void mma_s8(int* c, const uint32_t* a, const uint32_t* b) {
    asm volatile(
        "mma.sync.aligned.m16n8k32.row.col.s32.s8.s8.s32 "
        "{%0,%1,%2,%3}, {%4,%5,%6,%7}, {%8,%9}, {%0,%1,%2,%3};"
        : "+r"(c[0]), "+r"(c[1]), "+r"(c[2]), "+r"(c[3])
        : "r"(a[0]), "r"(a[1]), "r"(a[2]), "r"(a[3]), "r"(b[0]), "r"(b[1]));
}

// ---------------- block sum (256 threads) ----------------
__device__ __forceinline__ float block_sum_256(float v, float* sh) {
    #pragma unroll
    for (int o = 16; o; o >>= 1) v += __shfl_xor_sync(0xFFFFFFFFu, v, o);
    int tid = threadIdx.x;
    if ((tid & 31) == 0) sh[tid >> 5] = v;
    __syncthreads();
    if (tid < 8) {
        float t = sh[tid];
        #pragma unroll
        for (int o = 4; o; o >>= 1) t += __shfl_xor_sync(0x000000FFu, t, o);
        if (tid == 0) sh[8] = t;
    }
    __syncthreads();
    float r = sh[8];
    __syncthreads();
    return r;
}

// ---------------- weight scale: two-pass deterministic abs-mean ----------------
__global__ void __launch_bounds__(256) wabs_partial_kernel(const float* __restrict__ w) {
    __shared__ float sh[9];
    const float4* wf = (const float4*)w;
    float s = 0.0f;
    for (int i = blockIdx.x * 256 + threadIdx.x; i < (DIN / 4) * NOUT; i += 1024 * 256) {
        float4 t = wf[i];
        s += fabsf(t.x) + fabsf(t.y) + fabsf(t.z) + fabsf(t.w);
    }
    s = block_sum_256(s, sh);
    if (threadIdx.x == 0) g_partials[blockIdx.x] = s;
}
__global__ void __launch_bounds__(256) wabs_final_kernel() {
    __shared__ float sh[9];
    float s = 0.0f;
    for (int i = threadIdx.x; i < 1024; i += 256) s += g_partials[i];
    s = block_sum_256(s, sh);
    if (threadIdx.x == 0) {
        float mean = s * (1.0f / ((float)NOUT * (float)DIN));
        g_wscale = fmaxf(mean, 1e-5f);
    }
}

// ---------------- weight ternary quant -> int8 ----------------
__global__ void __launch_bounds__(256) wquant_kernel(const float* __restrict__ w) {
    float rws = 1.0f / g_wscale;
    const float4* wf = (const float4*)w;
    uint32_t* wq = (uint32_t*)g_wq;
    for (int i = blockIdx.x * 256 + threadIdx.x; i < (DIN / 4) * NOUT; i += 4096 * 256) {
        float4 t = wf[i];
        int q0 = (int)fminf(fmaxf(rintf(t.x * rws), -1.0f), 1.0f);
        int q1 = (int)fminf(fmaxf(rintf(t.y * rws), -1.0f), 1.0f);
        int q2 = (int)fminf(fmaxf(rintf(t.z * rws), -1.0f), 1.0f);
        int q3 = (int)fminf(fmaxf(rintf(t.w * rws), -1.0f), 1.0f);
        wq[i] = (q0 & 0xFF) | ((q1 & 0xFF) << 8) | ((q2 & 0xFF) << 16) | ((q3 & 0xFF) << 24);
    }
}

// ---------------- LayerNorm + per-token absmax int8 quant (single-pass stats) ----------------
__global__ void __launch_bounds__(256) ln_quant_kernel(const float* __restrict__ x) {
    __shared__ float sh_s[8], sh_s2[8], sh_mx[8], sh_mn[8];
    __shared__ float shb[4];  // mu, inv, rscale
    int row = blockIdx.x;
    int tid = threadIdx.x;
    const float4* xr = (const float4*)(x + (size_t)row * DIN);
    float4 v[4];
    #pragma unroll
    for (int c = 0; c < 4; c++) v[c] = xr[tid + c * 256];

    float s = 0.0f, s2 = 0.0f, mx = -1e30f, mn = 1e30f;
    #pragma unroll
    for (int c = 0; c < 4; c++) {
        s += v[c].x + v[c].y + v[c].z + v[c].w;
        s2 += v[c].x * v[c].x + v[c].y * v[c].y + v[c].z * v[c].z + v[c].w * v[c].w;
        mx = fmaxf(mx, fmaxf(fmaxf(v[c].x, v[c].y), fmaxf(v[c].z, v[c].w)));
        mn = fminf(mn, fminf(fminf(v[c].x, v[c].y), fminf(v[c].z, v[c].w)));
    }
    #pragma unroll
    for (int o = 16; o; o >>= 1) {
        s  += __shfl_xor_sync(0xFFFFFFFFu, s, o);
        s2 += __shfl_xor_sync(0xFFFFFFFFu, s2, o);
        mx = fmaxf(mx, __shfl_xor_sync(0xFFFFFFFFu, mx, o));
        mn = fminf(mn, __shfl_xor_sync(0xFFFFFFFFu, mn, o));
    }
    if ((tid & 31) == 0) {
        int w = tid >> 5;
        sh_s[w] = s; sh_s2[w] = s2; sh_mx[w] = mx; sh_mn[w] = mn;
    }
    __syncthreads();
    if (tid < 8) {
        float ts = sh_s[tid], ts2 = sh_s2[tid], tmx = sh_mx[tid], tmn = sh_mn[tid];
        #pragma unroll
        for (int o = 4; o; o >>= 1) {
            ts  += __shfl_xor_sync(0x000000FFu, ts, o);
            ts2 += __shfl_xor_sync(0x000000FFu, ts2, o);
            tmx = fmaxf(tmx, __shfl_xor_sync(0x000000FFu, tmx, o));
            tmn = fminf(tmn, __shfl_xor_sync(0x000000FFu, tmn, o));
        }
        if (tid == 0) {
            float mu = ts * (1.0f / DIN);
            float var = ts2 * (1.0f / DIN) - mu * mu + 1e-5f;
            float inv = rsqrtf(var);
            inv = inv * (1.5f - 0.5f * var * inv * inv);  // Newton refine
            float amax = fmaxf(tmx - mu, mu - tmn) * inv;
            float scale = fmaxf(amax, 1e-5f) * (1.0f / 127.0f);
            shb[0] = mu; shb[1] = inv; shb[2] = 1.0f / scale;
            g_xscale[row] = scale;
        }
    }
    __syncthreads();
    float mu = shb[0], inv = shb[1], rs = shb[2];
    float k = inv * rs;

    uint32_t* qrow = (uint32_t*)(g_xq + (size_t)row * DIN);
    #pragma unroll
    for (int c = 0; c < 4; c++) {
        int q0 = (int)fminf(fmaxf(rintf((v[c].x - mu) * k), -128.0f), 127.0f);
        int q1 = (int)fminf(fmaxf(rintf((v[c].y - mu) * k), -128.0f), 127.0f);
        int q2 = (int)fminf(fmaxf(rintf((v[c].z - mu) * k), -128.0f), 127.0f);
        int q3 = (int)fminf(fmaxf(rintf((v[c].w - mu) * k), -128.0f), 127.0f);
        qrow[tid + c * 256] = (q0 & 0xFF) | ((q1 & 0xFF) << 8) | ((q2 & 0xFF) << 16) |
                              ((q3 & 0xFF) << 24);
    }
}

// ---------------- int8 mma.sync GEMM: [8192,4096] x [4096,4096]^T ----------------
// CTA tile 128x128, warp tile 64x32 (8 warps 2x4), K chunk 64B, 5-stage cp.async,
// 2 CTAs/SM. SMEM rows padded to 80B -> ldmatrix phases conflict-free.
static constexpr int BM = 128, BN = 128, BK = 64, STAGES = 5;
static constexpr int NK = DIN / BK;          // 64
static constexpr int PITCH = 80;             // bytes per smem row
static constexpr int ASTG = BM * PITCH;      // 10240
static constexpr int BSTG = BN * PITCH;      // 10240
static constexpr int STG = ASTG + BSTG;      // 20480
static constexpr int GEMM_SMEM = STAGES * STG;  // 102400

__device__ __forceinline__ void copy_stage(uint32_t sb, int s, int kc,
                                           const signed char* Ab,
                                           const signed char* Bb, int tid) {
    uint32_t stA = sb + s * STG;
    uint32_t stB = stA + ASTG;
    #pragma unroll
    for (int p = 0; p < 2; ++p) {  // A: 128 rows x 4 granules = 512
        int g = tid + p * 256;
        int r = g >> 2, c = g & 3;
        cp_async16(stA + r * PITCH + c * 16, Ab + (size_t)r * DIN + kc * BK + c * 16);
    }
    #pragma unroll
    for (int p = 0; p < 2; ++p) {  // B: 128 rows x 4 granules
        int g = tid + p * 256;
        int r = g >> 2, c = g & 3;
        cp_async16(stB + r * PITCH + c * 16, Bb + (size_t)r * DIN + kc * BK + c * 16);
    }
}

__global__ void __launch_bounds__(256, 2) gemm_kernel(float* __restrict__ out) {
    extern __shared__ __align__(128) char smem[];
    uint32_t sb = smem_u32(smem);
    int tid = threadIdx.x, wid = tid >> 5, lane = tid & 31;
    int nt = blockIdx.x, mt = blockIdx.y;
    int warp_m = wid >> 2;   // 0..1  -> 64-row slab
    int warp_n = wid & 3;    // 0..3  -> 32-col slab

    const signed char* Ab = g_xq + (size_t)mt * BM * DIN;
    const signed char* Bb = g_wq + (size_t)nt * BN * DIN;

    // ldmatrix lane-address offsets (within a stage)
    uint32_t aoff = (uint32_t)(warp_m * 64 + (lane & 15)) * PITCH + (uint32_t)(lane >> 4) * 16;
    uint32_t boff = (uint32_t)(warp_n * 32 + ((lane >> 4) & 1) * 8 + (lane & 7)) * PITCH +
                    (uint32_t)((lane >> 3) & 1) * 16;

    int acc[4][4][4];
    #pragma unroll
    for (int i = 0; i < 4; i++)
        #pragma unroll
        for (int j = 0; j < 4; j++)
            #pragma unroll
            for (int k = 0; k < 4; k++) acc[i][j][k] = 0;

    // prologue: stages 0..STAGES-2
    #pragma unroll
    for (int s = 0; s < STAGES - 1; ++s) {
        copy_stage(sb, s, s, Ab, Bb, tid);
        CP_COMMIT();
    }

    for (int i = 0; i < NK; ++i) {
        CP_WAIT(STAGES - 2);
        __syncthreads();

        int j = i + (STAGES - 1);
        if (j < NK) copy_stage(sb, j % STAGES, j, Ab, Bb, tid);
        CP_COMMIT();  // commit every iter (possibly empty) to keep group count invariant

        int s = i % STAGES;
        uint32_t stA = sb + s * STG;
        uint32_t stB = stA + ASTG;
        #pragma unroll
        for (int ks = 0; ks < 2; ++ks) {  // two k32 substeps per 64B chunk
            uint32_t a[4][4];
            uint32_t b[4][2];
            #pragma unroll
            for (int im = 0; im < 4; ++im)
                ldsm_x4(a[im][0], a[im][1], a[im][2], a[im][3],
                        stA + aoff + im * 16 * PITCH + ks * 32);
            #pragma unroll
            for (int t = 0; t < 2; ++t)
                ldsm_x4(b[2 * t][0], b[2 * t][1], b[2 * t + 1][0], b[2 * t + 1][1],
                        stB + boff + t * 16 * PITCH + ks * 32);
            #pragma unroll
            for (int im = 0; im < 4; ++im)
                #pragma unroll
                for (int in = 0; in < 4; ++in)
                    mma_s8(acc[im][in], a[im], b[in]);
        }
    }

    // epilogue: s32 -> f32 with w_scale * x_scale[m]
    float ws = g_wscale;
    int m0 = mt * BM + warp_m * 64 + (lane >> 2);
    int n0 = nt * BN + warp_n * 32 + (lane & 3) * 2;
    #pragma unroll
    for (int im = 0; im < 4; ++im) {
        int r0 = m0 + im * 16;
        int r1 = r0 + 8;
        float f0 = ws * g_xscale[r0];
        float f1 = ws * g_xscale[r1];
        float* o0 = out + (size_t)r0 * NOUT + n0;
        float* o1 = out + (size_t)r1 * NOUT + n0;
        #pragma unroll
        for (int in = 0; in < 4; ++in) {
            float2 v0, v1;
            v0.x = (float)acc[im][in][0] * f0;
            v0.y = (float)acc[im][in][1] * f0;
            v1.x = (float)acc[im][in][2] * f1;
            v1.y = (float)acc[im][in][3] * f1;
            *(float2*)(o0 + in * 8) = v0;
            *(float2*)(o1 + in * 8) = v1;
        }
    }
}

// ---------------- launch ----------------
extern "C" void kernel_launch(void* const* d_in, const int* in_sizes, int n_in,
                              void* d_out, int out_size) {
    const float* x = (const float*)d_in[0];
    const float* w = (const float*)d_in[1];
    float* out = (float*)d_out;

    cudaFuncSetAttribute(gemm_kernel, cudaFuncAttributeMaxDynamicSharedMemorySize, GEMM_SMEM);

    wabs_partial_kernel<<<1024, 256>>>(w);
    wabs_final_kernel<<<1, 256>>>();
    wquant_kernel<<<4096, 256>>>(w);
    ln_quant_kernel<<<NROWS, 256>>>(x);
    gemm_kernel<<<dim3(NOUT / BN, NROWS / BM), 256, GEMM_SMEM>>>(out);
}